// round 5
// baseline (speedup 1.0000x reference)
#include <cuda_runtime.h>
#include <math.h>

#define T    2048
#define F    1024
#define NB   64          // total batch
#define HB   32          // half batch
#define KSEL 20
#define BPB  256         // blocks per batch (2048 rows / 8 rows-per-block)

// scratch (no allocs allowed) — zero-init; reset at end of every launch
__device__ float g_mags[NB * T];
__device__ int   g_idx[NB * KSEL];
__device__ int   g_cnt[NB];
__device__ volatile int g_flag[NB];
__device__ int   g_done;

__global__ void __launch_bounds__(256)
fused_kernel(const float* __restrict__ feat,
             const float* __restrict__ scores,
             const float* __restrict__ mask_abn,
             const float* __restrict__ mask_nor,
             float* __restrict__ out) {
    int blk   = blockIdx.x;
    int batch = blk >> 8;          // 256 blocks per batch
    int slice = blk & 255;
    int tid   = threadIdx.x;
    int lane  = tid & 31;
    int wid   = tid >> 5;

    // ---------------- phase 1: L2 norms for 8 rows (one warp per row) ------
    {
        int t = slice * 8 + wid;
        const float4* row = (const float4*)(feat + ((size_t)batch * T + t) * F);
        float s = 0.f;
#pragma unroll
        for (int i = 0; i < 8; i++) {
            float4 v = row[lane + i * 32];
            s += v.x * v.x + v.y * v.y + v.z * v.z + v.w * v.w;
        }
#pragma unroll
        for (int o = 16; o; o >>= 1) s += __shfl_xor_sync(0xffffffffu, s, o);
        if (lane == 0) g_mags[batch * T + t] = sqrtf(s);
    }
    __syncthreads();

    // ---------------- completion count: am I the last block of this batch? -
    __shared__ int s_last;
    if (tid == 0) {
        __threadfence();                       // release my mag stores
        int c = atomicAdd(&g_cnt[batch], 1);
        s_last = (c == BPB - 1);
    }
    __syncthreads();

    int r = (batch >= HB) ? (batch - HB) : (batch + HB);  // output row

    // ---------------- phase 2: top-K by the last block of the batch --------
    if (s_last) {
        __shared__ float wrv[8];
        __shared__ int   wri[8];
        __shared__ int   s_win;
        __shared__ int   s_idx[KSEL];
        __shared__ float s_sc[KSEL];

        __threadfence();                       // acquire other blocks' mags

        const float* mask = (batch >= HB) ? mask_abn + (size_t)(batch - HB) * T
                                          : mask_nor + (size_t)batch * T;
        const float inv = 1.0f / 0.9f;         // 1/(1-P)
        float v[8];
#pragma unroll
        for (int j = 0; j < 8; j++) {
            int t = tid + j * 256;
            float d = (mask[t] > 0.1f) ? inv : 0.0f;
            // __ldcg: mags were written by other SMs this launch; bypass L1
            v[j] = __ldcg(&g_mags[batch * T + t]) * d;
        }

        for (int k = 0; k < KSEL; k++) {
            // local argmax (ascending index + strict '>' => lowest idx on tie)
            float bv = -1.0f; int bi = 1 << 30;
#pragma unroll
            for (int j = 0; j < 8; j++) {
                if (v[j] > bv) { bv = v[j]; bi = tid + j * 256; }
            }
#pragma unroll
            for (int o = 16; o; o >>= 1) {
                float ov = __shfl_xor_sync(0xffffffffu, bv, o);
                int   oi = __shfl_xor_sync(0xffffffffu, bi, o);
                if (ov > bv || (ov == bv && oi < bi)) { bv = ov; bi = oi; }
            }
            if (lane == 0) { wrv[wid] = bv; wri[wid] = bi; }
            __syncthreads();
            if (wid == 0) {
                float fv = (lane < 8) ? wrv[lane] : -2.0f;
                int   fi = (lane < 8) ? wri[lane] : (1 << 30);
#pragma unroll
                for (int o = 4; o; o >>= 1) {
                    float ov = __shfl_xor_sync(0xffffffffu, fv, o);
                    int   oi = __shfl_xor_sync(0xffffffffu, fi, o);
                    if (ov > fv || (ov == fv && oi < fi)) { fv = ov; fi = oi; }
                }
                if (lane == 0) { s_idx[k] = fi; s_win = fi; }
            }
            __syncthreads();
            int w = s_win;
            if ((w & 255) == tid) v[w >> 8] = -1.0f;  // remove winner (vals >= 0)
        }

        // indices out + score mean (single parallel load pass)
        if (tid < KSEL) {
            int idx = s_idx[tid];
            g_idx[r * KSEL + tid] = idx;
            s_sc[tid] = scores[(size_t)batch * T + idx];
        }
        __syncthreads();
        if (tid == 0) {
            float s = 0.f;
#pragma unroll
            for (int k = 0; k < KSEL; k++) s += s_sc[k];
            out[r] = s / (float)KSEL;   // [0,32)=score_abnormal, [32,64)=score_normal
            __threadfence();            // release g_idx before raising flag
            g_flag[batch] = 1;
        }
    }

    // ---------------- phase 3: gather (first 20 blocks of each batch) ------
    if (slice < KSEL) {
        if (tid == 0) {
            while (g_flag[batch] == 0) __nanosleep(64);
        }
        __syncthreads();
        __threadfence();                                   // acquire g_idx
        int idx = __ldcg(&g_idx[r * KSEL + slice]);        // bypass L1 (cross-SM)
        const float4* src = (const float4*)(feat + ((size_t)batch * T + idx) * F);
        float4* dst = (float4*)(out + 64 + ((size_t)r * KSEL + slice) * F);
        dst[tid] = src[tid];

        // ---------- replay-safe reset by the globally last gather block ----
        if (tid == 0) {
            __threadfence();
            int d = atomicAdd(&g_done, 1);
            if (d == NB * KSEL - 1) {
#pragma unroll
                for (int i = 0; i < NB; i++) { g_cnt[i] = 0; g_flag[i] = 0; }
                g_done = 0;
            }
        }
    }
}

extern "C" void kernel_launch(void* const* d_in, const int* in_sizes, int n_in,
                              void* d_out, int out_size) {
    const float* feat   = (const float*)d_in[0];
    const float* scores = (const float*)d_in[1];
    const float* mabn   = (const float*)d_in[2];
    const float* mnor   = (const float*)d_in[3];
    float* out = (float*)d_out;

    fused_kernel<<<NB * BPB, 256>>>(feat, scores, mabn, mnor, out);
}

// round 6
// speedup vs baseline: 1.0023x; 1.0023x over previous
#include <cuda_runtime.h>
#include <math.h>

#define T    2048
#define F    1024
#define NB   64          // total batch
#define HB   32          // half batch
#define KSEL 20
#define BPB  256         // blocks per batch (2048 rows / 8 rows-per-block)

// scratch (no allocs allowed) — zero-init; reset at end of every launch
__device__ float g_mags[NB * T];
__device__ int   g_idx[NB * KSEL];
__device__ int   g_cnt[NB];
__device__ volatile int g_flag[NB];
__device__ int   g_done;

__global__ void __launch_bounds__(256)
fused_kernel(const float* __restrict__ feat,
             const float* __restrict__ scores,
             const float* __restrict__ mask_abn,
             const float* __restrict__ mask_nor,
             float* __restrict__ out) {
    int blk   = blockIdx.x;
    int batch = blk >> 8;          // 256 blocks per batch
    int slice = blk & 255;
    int tid   = threadIdx.x;
    int lane  = tid & 31;
    int wid   = tid >> 5;

    // ---------------- phase 1: L2 norms for 8 rows (one warp per row) ------
    {
        int t = slice * 8 + wid;
        const float4* row = (const float4*)(feat + ((size_t)batch * T + t) * F);
        float s = 0.f;
#pragma unroll
        for (int i = 0; i < 8; i++) {
            float4 v = row[lane + i * 32];
            s += v.x * v.x + v.y * v.y + v.z * v.z + v.w * v.w;
        }
#pragma unroll
        for (int o = 16; o; o >>= 1) s += __shfl_xor_sync(0xffffffffu, s, o);
        if (lane == 0) g_mags[batch * T + t] = sqrtf(s);
    }
    __syncthreads();

    // ---------------- completion count: am I the last block of this batch? -
    __shared__ int s_last;
    if (tid == 0) {
        __threadfence();                       // release my mag stores
        int c = atomicAdd(&g_cnt[batch], 1);
        s_last = (c == BPB - 1);
    }
    __syncthreads();

    int r = (batch >= HB) ? (batch - HB) : (batch + HB);  // output row

    // ---------------- phase 2: top-K by the last block of the batch --------
    if (s_last) {
        __shared__ float wrv[8];
        __shared__ int   wri[8];
        __shared__ int   s_win;
        __shared__ int   s_idx[KSEL];
        __shared__ float s_sc[KSEL];

        __threadfence();                       // acquire other blocks' mags

        const float* mask = (batch >= HB) ? mask_abn + (size_t)(batch - HB) * T
                                          : mask_nor + (size_t)batch * T;
        const float inv = 1.0f / 0.9f;         // 1/(1-P)
        float v[8];
#pragma unroll
        for (int j = 0; j < 8; j++) {
            int t = tid + j * 256;
            float d = (mask[t] > 0.1f) ? inv : 0.0f;
            // __ldcg: mags were written by other SMs this launch; bypass L1
            v[j] = __ldcg(&g_mags[batch * T + t]) * d;
        }

        for (int k = 0; k < KSEL; k++) {
            // local argmax (ascending index + strict '>' => lowest idx on tie)
            float bv = -1.0f; int bi = 1 << 30;
#pragma unroll
            for (int j = 0; j < 8; j++) {
                if (v[j] > bv) { bv = v[j]; bi = tid + j * 256; }
            }
#pragma unroll
            for (int o = 16; o; o >>= 1) {
                float ov = __shfl_xor_sync(0xffffffffu, bv, o);
                int   oi = __shfl_xor_sync(0xffffffffu, bi, o);
                if (ov > bv || (ov == bv && oi < bi)) { bv = ov; bi = oi; }
            }
            if (lane == 0) { wrv[wid] = bv; wri[wid] = bi; }
            __syncthreads();
            if (wid == 0) {
                float fv = (lane < 8) ? wrv[lane] : -2.0f;
                int   fi = (lane < 8) ? wri[lane] : (1 << 30);
#pragma unroll
                for (int o = 4; o; o >>= 1) {
                    float ov = __shfl_xor_sync(0xffffffffu, fv, o);
                    int   oi = __shfl_xor_sync(0xffffffffu, fi, o);
                    if (ov > fv || (ov == fv && oi < fi)) { fv = ov; fi = oi; }
                }
                if (lane == 0) { s_idx[k] = fi; s_win = fi; }
            }
            __syncthreads();
            int w = s_win;
            if ((w & 255) == tid) v[w >> 8] = -1.0f;  // remove winner (vals >= 0)
        }

        // indices out + score mean (single parallel load pass)
        if (tid < KSEL) {
            int idx = s_idx[tid];
            g_idx[r * KSEL + tid] = idx;
            s_sc[tid] = scores[(size_t)batch * T + idx];
        }
        __syncthreads();
        if (tid == 0) {
            float s = 0.f;
#pragma unroll
            for (int k = 0; k < KSEL; k++) s += s_sc[k];
            out[r] = s / (float)KSEL;   // [0,32)=score_abnormal, [32,64)=score_normal
            __threadfence();            // release g_idx before raising flag
            g_flag[batch] = 1;
        }
    }

    // ---------------- phase 3: gather (first 20 blocks of each batch) ------
    if (slice < KSEL) {
        if (tid == 0) {
            while (g_flag[batch] == 0) __nanosleep(64);
        }
        __syncthreads();
        __threadfence();                                   // acquire g_idx
        int idx = __ldcg(&g_idx[r * KSEL + slice]);        // bypass L1 (cross-SM)
        const float4* src = (const float4*)(feat + ((size_t)batch * T + idx) * F);
        float4* dst = (float4*)(out + 64 + ((size_t)r * KSEL + slice) * F);
        dst[tid] = src[tid];

        // ---------- replay-safe reset by the globally last gather block ----
        if (tid == 0) {
            __threadfence();
            int d = atomicAdd(&g_done, 1);
            if (d == NB * KSEL - 1) {
#pragma unroll
                for (int i = 0; i < NB; i++) { g_cnt[i] = 0; g_flag[i] = 0; }
                g_done = 0;
            }
        }
    }
}

extern "C" void kernel_launch(void* const* d_in, const int* in_sizes, int n_in,
                              void* d_out, int out_size) {
    const float* feat   = (const float*)d_in[0];
    const float* scores = (const float*)d_in[1];
    const float* mabn   = (const float*)d_in[2];
    const float* mnor   = (const float*)d_in[3];
    float* out = (float*)d_out;

    fused_kernel<<<NB * BPB, 256>>>(feat, scores, mabn, mnor, out);
}

// round 7
// speedup vs baseline: 1.0289x; 1.0265x over previous
#include <cuda_runtime.h>
#include <math.h>

#define T    2048
#define F    1024
#define NB   64          // total batch
#define HB   32          // half batch
#define KSEL 20
#define BPB  256         // blocks per batch (2048 rows / 8 rows-per-block)
#define GRID (NB * BPB)          // 16384
#define NGATHER (NB * KSEL)      // 1280
#define GATHER_BASE (GRID - NGATHER)  // 15104 — gather duty on LAST wave blocks

// scratch (no allocs allowed) — zero-init; reset at end of every launch
__device__ float g_mags[NB * T];
__device__ int   g_idx[NB * KSEL];
__device__ int   g_cnt[NB];
__device__ volatile int g_flag[NB];
__device__ int   g_done;

__global__ void __launch_bounds__(256)
fused_kernel(const float* __restrict__ feat,
             const float* __restrict__ scores,
             const float* __restrict__ mask_abn,
             const float* __restrict__ mask_nor,
             float* __restrict__ out) {
    int blk   = blockIdx.x;
    int batch = blk >> 8;          // 256 consecutive blocks per batch
    int slice = blk & 255;
    int tid   = threadIdx.x;
    int lane  = tid & 31;
    int wid   = tid >> 5;

    // ---------------- phase 1: L2 norms for 8 rows (one warp per row) ------
    {
        int t = slice * 8 + wid;
        const float4* row = (const float4*)(feat + ((size_t)batch * T + t) * F);
        float s = 0.f;
#pragma unroll
        for (int i = 0; i < 8; i++) {
            float4 v = row[lane + i * 32];
            s += v.x * v.x + v.y * v.y + v.z * v.z + v.w * v.w;
        }
#pragma unroll
        for (int o = 16; o; o >>= 1) s += __shfl_xor_sync(0xffffffffu, s, o);
        if (lane == 0) g_mags[batch * T + t] = sqrtf(s);
    }
    __syncthreads();

    // ---------------- completion count: am I the last block of this batch? -
    __shared__ int s_last;
    if (tid == 0) {
        __threadfence();                       // release my mag stores
        int c = atomicAdd(&g_cnt[batch], 1);
        s_last = (c == BPB - 1);
    }
    __syncthreads();

    // ---------------- phase 2: top-K by the last-arriving block of batch ---
    if (s_last) {
        __shared__ float wrv[8];
        __shared__ int   wri[8];
        __shared__ int   s_win;
        __shared__ int   s_idx[KSEL];
        __shared__ float s_sc[KSEL];

        int r = (batch >= HB) ? (batch - HB) : (batch + HB);  // output row
        __threadfence();                       // acquire other blocks' mags

        const float* mask = (batch >= HB) ? mask_abn + (size_t)(batch - HB) * T
                                          : mask_nor + (size_t)batch * T;
        const float inv = 1.0f / 0.9f;         // 1/(1-P)
        float v[8];
#pragma unroll
        for (int j = 0; j < 8; j++) {
            int t = tid + j * 256;
            float d = (mask[t] > 0.1f) ? inv : 0.0f;
            v[j] = __ldcg(&g_mags[batch * T + t]) * d;  // bypass L1 (cross-SM)
        }

        for (int k = 0; k < KSEL; k++) {
            // local argmax (ascending index + strict '>' => lowest idx on tie)
            float bv = -1.0f; int bi = 1 << 30;
#pragma unroll
            for (int j = 0; j < 8; j++) {
                if (v[j] > bv) { bv = v[j]; bi = tid + j * 256; }
            }
#pragma unroll
            for (int o = 16; o; o >>= 1) {
                float ov = __shfl_xor_sync(0xffffffffu, bv, o);
                int   oi = __shfl_xor_sync(0xffffffffu, bi, o);
                if (ov > bv || (ov == bv && oi < bi)) { bv = ov; bi = oi; }
            }
            if (lane == 0) { wrv[wid] = bv; wri[wid] = bi; }
            __syncthreads();
            if (wid == 0) {
                float fv = (lane < 8) ? wrv[lane] : -2.0f;
                int   fi = (lane < 8) ? wri[lane] : (1 << 30);
#pragma unroll
                for (int o = 4; o; o >>= 1) {
                    float ov = __shfl_xor_sync(0xffffffffu, fv, o);
                    int   oi = __shfl_xor_sync(0xffffffffu, fi, o);
                    if (ov > fv || (ov == fv && oi < fi)) { fv = ov; fi = oi; }
                }
                if (lane == 0) { s_idx[k] = fi; s_win = fi; }
            }
            __syncthreads();
            int w = s_win;
            if ((w & 255) == tid) v[w >> 8] = -1.0f;  // remove winner (vals >= 0)
        }

        // indices out + score mean (single parallel load pass)
        if (tid < KSEL) {
            int idx = s_idx[tid];
            g_idx[r * KSEL + tid] = idx;
            s_sc[tid] = scores[(size_t)batch * T + idx];
        }
        __syncthreads();
        if (tid == 0) {
            float s = 0.f;
#pragma unroll
            for (int k = 0; k < KSEL; k++) s += s_sc[k];
            out[r] = s / (float)KSEL;   // [0,32)=score_abnormal, [32,64)=score_normal
            __threadfence();            // release g_idx before raising flag
            g_flag[batch] = 1;
        }
    }

    // ---------------- phase 3: gather by the LAST 1280 blocks of the grid --
    // These run in the final wave; nearly all flags are already set, so spin
    // time ~0 and no mag work is blocked behind spinners (the R6 mistake).
    if (blk >= GATHER_BASE) {
        int u  = blk - GATHER_BASE;      // 0..1279 gather unit
        int r  = u / KSEL;               // output row 0..63 (abn rows first)
        int k  = u % KSEL;
        int gb = (r < HB) ? (HB + r) : (r - HB);   // source batch of this row

        if (tid == 0) {
            while (g_flag[gb] == 0) __nanosleep(64);
        }
        __syncthreads();
        __threadfence();                                   // acquire g_idx
        int idx = __ldcg(&g_idx[r * KSEL + k]);            // bypass L1 (cross-SM)
        const float4* src = (const float4*)(feat + ((size_t)gb * T + idx) * F);
        float4* dst = (float4*)(out + 64 + ((size_t)r * KSEL + k) * F);
        dst[tid] = src[tid];

        // ---------- replay-safe reset by the globally last gather block ----
        if (tid == 0) {
            __threadfence();
            int d = atomicAdd(&g_done, 1);
            if (d == NGATHER - 1) {
#pragma unroll
                for (int i = 0; i < NB; i++) { g_cnt[i] = 0; g_flag[i] = 0; }
                g_done = 0;
            }
        }
    }
}

extern "C" void kernel_launch(void* const* d_in, const int* in_sizes, int n_in,
                              void* d_out, int out_size) {
    const float* feat   = (const float*)d_in[0];
    const float* scores = (const float*)d_in[1];
    const float* mabn   = (const float*)d_in[2];
    const float* mnor   = (const float*)d_in[3];
    float* out = (float*)d_out;

    fused_kernel<<<GRID, 256>>>(feat, scores, mabn, mnor, out);
}